// round 10
// baseline (speedup 1.0000x reference)
#include <cuda_runtime.h>
#include <cstdint>

#define BATCH 4
#define SEQ   4096
#define EMB   384
#define HDIM  64
#define BM    128
#define BN    128
#define NTQ   (SEQ / BM)          // 32 q tiles per batch
#define KST   68                  // K/V/Q padded row stride (floats)
#define PST   132                 // P padded row stride (floats, 128 rows + 4)

// smem layout (float offsets)
#define KS_OFF 0                              // K double buffer: 2*128*68 = 17408
#define VS_OFF (2 * BN * KST)                 // 17408; V single buffer: 8704
#define QS_OFF (VS_OFF + BN * KST)            // 26112; Q: 8704
#define PS_OFF (QS_OFF + BM * KST)            // 34816; P: 128*132 = 16896
#define SMEM_FLOATS (PS_OFF + BN * PST)       // 51712
#define SMEM_BYTES  (SMEM_FLOATS * 4)         // 206848

__device__ float g_q[BATCH * SEQ * HDIM];
__device__ float g_k[BATCH * SEQ * HDIM];
__device__ float g_v[BATCH * SEQ * HDIM];

__device__ __forceinline__ void cp16(unsigned int saddr, const void* gptr) {
    asm volatile("cp.async.cg.shared.global [%0], [%1], 16;" :: "r"(saddr), "l"(gptr));
}
__device__ __forceinline__ void cp_commit() {
    asm volatile("cp.async.commit_group;");
}

// ---------------- fused QKV projection: 32 rows/block ----------------
__global__ __launch_bounds__(192) void qkv_proj(const float* __restrict__ x,
                                                const float* __restrict__ Wq,
                                                const float* __restrict__ Wk,
                                                const float* __restrict__ Wv) {
    __shared__ float4 xs4[32 * 96];   // 48 KB
    const int tid = threadIdx.x;
    const size_t row0 = (size_t)blockIdx.x * 32;

    const float4* xsrc = (const float4*)(x + row0 * EMB);
#pragma unroll
    for (int i = 0; i < 16; i++) xs4[tid + i * 192] = xsrc[tid + i * 192];
    __syncthreads();

    const int mat = tid >> 6;
    const int col = tid & 63;
    const float* W = (mat == 0) ? Wq : (mat == 1 ? Wk : Wv);
    float* dst     = (mat == 0) ? g_q : (mat == 1 ? g_k : g_v);

    float acc[32];
#pragma unroll
    for (int r = 0; r < 32; r++) acc[r] = 0.f;

#pragma unroll 2
    for (int e4 = 0; e4 < 96; e4++) {
        const float w0 = W[(e4 * 4 + 0) * HDIM + col];
        const float w1 = W[(e4 * 4 + 1) * HDIM + col];
        const float w2 = W[(e4 * 4 + 2) * HDIM + col];
        const float w3 = W[(e4 * 4 + 3) * HDIM + col];
#pragma unroll
        for (int r = 0; r < 32; r++) {
            const float4 xv = xs4[r * 96 + e4];
            acc[r] = fmaf(xv.x, w0, fmaf(xv.y, w1, fmaf(xv.z, w2, fmaf(xv.w, w3, acc[r]))));
        }
    }
#pragma unroll
    for (int r = 0; r < 32; r++)
        dst[(row0 + r) * HDIM + col] = acc[r];
}

// ---------------- causal flash attention, 128x128 tile, 8x8 register tiles ----------------
// 256 threads: trow=tid>>4 (16 groups of 8 rows), tcol=tid&15.
// cp.async groups: V(kt) committed before K(kt+1); S waits K(kt), PV waits V(kt).
__global__ __launch_bounds__(256, 1) void flash_fwd(float* __restrict__ out) {
    extern __shared__ float sm[];
    const int tid  = threadIdx.x;
    const int b    = blockIdx.x & 3;
    const int qt   = blockIdx.x >> 2;      // 0..31
    const int trow = tid >> 4;
    const int tcol = tid & 15;
    const int r0   = trow * 8;
    const int sx0  = (tcol >> 3) * 64;
    const int dmb  = (tcol & 7) * 8;
    const float NEG_INF = __int_as_float(0xff800000);
    const size_t base = (size_t)b * SEQ * HDIM;
    const unsigned int smb = (unsigned int)__cvta_generic_to_shared(sm);

    const int nkt = qt + 1;

    // stage Q tile (scaled by 1/8): 2048 float4, 8 per thread
    {
        const float4* qsrc = (const float4*)(g_q + base + (size_t)qt * BM * HDIM);
#pragma unroll
        for (int j = 0; j < 8; j++) {
            const int idx = tid + 256 * j;       // 0..2047
            const int row = idx >> 4, c4 = idx & 15;
            float4 v = qsrc[idx];
            v.x *= 0.125f; v.y *= 0.125f; v.z *= 0.125f; v.w *= 0.125f;
            *(float4*)&sm[QS_OFF + row * KST + c4 * 4] = v;
        }
    }

    float o[8][8];
#pragma unroll
    for (int i = 0; i < 8; i++)
#pragma unroll
        for (int d = 0; d < 8; d++) o[i][d] = 0.f;
    float m[8], l[8];
#pragma unroll
    for (int i = 0; i < 8; i++) { m[i] = NEG_INF; l[i] = 0.f; }

    // prologue: commit K0 (group), then V0 (group)
    {
        const float* kg = g_k + base;
#pragma unroll
        for (int j = 0; j < 8; j++) {
            const int idx = tid + 256 * j;
            const int row = idx >> 4, c4 = idx & 15;
            cp16(smb + (unsigned int)((KS_OFF + row * KST + c4 * 4) << 2), kg + idx * 4);
        }
        cp_commit();
        const float* vg = g_v + base;
#pragma unroll
        for (int j = 0; j < 8; j++) {
            const int idx = tid + 256 * j;
            const int row = idx >> 4, c4 = idx & 15;
            cp16(smb + (unsigned int)((VS_OFF + row * KST + c4 * 4) << 2), vg + idx * 4);
        }
        cp_commit();
    }

    for (int kt = 0; kt < nkt; kt++) {
        const int cur  = kt & 1;
        const bool last = (kt + 1 == nkt);
        __syncthreads();   // Q staged / K[cur^1] free / PV(kt-1) done (V,P free)

        if (kt > 0) {      // V(kt) into the single V buffer
            const float* vg = g_v + base + (size_t)kt * BN * HDIM;
#pragma unroll
            for (int j = 0; j < 8; j++) {
                const int idx = tid + 256 * j;
                const int row = idx >> 4, c4 = idx & 15;
                cp16(smb + (unsigned int)((VS_OFF + row * KST + c4 * 4) << 2), vg + idx * 4);
            }
            cp_commit();
        }
        if (!last) {       // K(kt+1) into stage cur^1
            const float* kg = g_k + base + (size_t)(kt + 1) * BN * HDIM;
#pragma unroll
            for (int j = 0; j < 8; j++) {
                const int idx = tid + 256 * j;
                const int row = idx >> 4, c4 = idx & 15;
                cp16(smb + (unsigned int)((KS_OFF + ((cur ^ 1) * BN + row) * KST + c4 * 4) << 2), kg + idx * 4);
            }
            cp_commit();
        }

        // wait for K(kt): leave {V(kt), K(kt+1)} or {V(kt)} outstanding
        if (!last) asm volatile("cp.async.wait_group 2;");
        else       asm volatile("cp.async.wait_group 1;");
        __syncthreads();

        // ---- S = Q K^T (8 rows x 8 cols per thread) ----
        float s[8][8];
#pragma unroll
        for (int i = 0; i < 8; i++)
#pragma unroll
            for (int j = 0; j < 8; j++) s[i][j] = 0.f;

        const float* Kst = sm + KS_OFF + cur * BN * KST;
        for (int k4 = 0; k4 < 16; k4++) {
            float4 kv[8];
#pragma unroll
            for (int jj = 0; jj < 8; jj++)
                kv[jj] = *(const float4*)&Kst[(jj * 16 + tcol) * KST + k4 * 4];
#pragma unroll
            for (int i = 0; i < 8; i++) {
                const float4 q = *(const float4*)&sm[QS_OFF + (r0 + i) * KST + k4 * 4];
#pragma unroll
                for (int jj = 0; jj < 8; jj++) {
                    s[i][jj] = fmaf(q.x, kv[jj].x,
                               fmaf(q.y, kv[jj].y,
                               fmaf(q.z, kv[jj].z,
                               fmaf(q.w, kv[jj].w, s[i][jj]))));
                }
            }
        }

        if (last) {  // diagonal tile: causal mask
#pragma unroll
            for (int i = 0; i < 8; i++) {
                const int row = qt * BM + r0 + i;
#pragma unroll
                for (int jj = 0; jj < 8; jj++)
                    if (kt * BN + jj * 16 + tcol > row) s[i][jj] = NEG_INF;
            }
        }

        // ---- online softmax (row group = 16 lanes sharing trow) ----
#pragma unroll
        for (int i = 0; i < 8; i++) {
            float tm = s[i][0];
#pragma unroll
            for (int jj = 1; jj < 8; jj++) tm = fmaxf(tm, s[i][jj]);
            tm = fmaxf(tm, __shfl_xor_sync(0xffffffffu, tm, 1));
            tm = fmaxf(tm, __shfl_xor_sync(0xffffffffu, tm, 2));
            tm = fmaxf(tm, __shfl_xor_sync(0xffffffffu, tm, 4));
            tm = fmaxf(tm, __shfl_xor_sync(0xffffffffu, tm, 8));
            const float mnew  = fmaxf(m[i], tm);
            const float alpha = __expf(m[i] - mnew);
            float sum = 0.f;
#pragma unroll
            for (int jj = 0; jj < 8; jj++) {
                s[i][jj] = __expf(s[i][jj] - mnew);
                sum += s[i][jj];
            }
            sum += __shfl_xor_sync(0xffffffffu, sum, 1);
            sum += __shfl_xor_sync(0xffffffffu, sum, 2);
            sum += __shfl_xor_sync(0xffffffffu, sum, 4);
            sum += __shfl_xor_sync(0xffffffffu, sum, 8);
            l[i] = l[i] * alpha + sum;
            m[i] = mnew;
#pragma unroll
            for (int d = 0; d < 8; d++) o[i][d] *= alpha;
        }

        // write P transposed: Ps[col][row], stride PST
#pragma unroll
        for (int jj = 0; jj < 8; jj++) {
            *(float4*)&sm[PS_OFF + (jj * 16 + tcol) * PST + r0] =
                make_float4(s[0][jj], s[1][jj], s[2][jj], s[3][jj]);
            *(float4*)&sm[PS_OFF + (jj * 16 + tcol) * PST + r0 + 4] =
                make_float4(s[4][jj], s[5][jj], s[6][jj], s[7][jj]);
        }

        // wait for V(kt): leave {K(kt+1)} or {} outstanding; sync also publishes P
        if (!last) asm volatile("cp.async.wait_group 1;");
        else       asm volatile("cp.async.wait_group 0;");
        __syncthreads();

        // ---- O += P V over this thread's sx half ----
        const float* Vst = sm + VS_OFF;
#pragma unroll 4
        for (int u = 0; u < 64; u++) {
            const int sx = sx0 + u;
            const float4 pa = *(const float4*)&sm[PS_OFF + sx * PST + r0];
            const float4 pb = *(const float4*)&sm[PS_OFF + sx * PST + r0 + 4];
            const float4 va = *(const float4*)&Vst[sx * KST + dmb];
            const float4 vb = *(const float4*)&Vst[sx * KST + dmb + 4];
            const float pr[8] = {pa.x, pa.y, pa.z, pa.w, pb.x, pb.y, pb.z, pb.w};
#pragma unroll
            for (int i = 0; i < 8; i++) {
                o[i][0] = fmaf(pr[i], va.x, o[i][0]);
                o[i][1] = fmaf(pr[i], va.y, o[i][1]);
                o[i][2] = fmaf(pr[i], va.z, o[i][2]);
                o[i][3] = fmaf(pr[i], va.w, o[i][3]);
                o[i][4] = fmaf(pr[i], vb.x, o[i][4]);
                o[i][5] = fmaf(pr[i], vb.y, o[i][5]);
                o[i][6] = fmaf(pr[i], vb.z, o[i][6]);
                o[i][7] = fmaf(pr[i], vb.w, o[i][7]);
            }
        }
    }

    // combine the two sx halves (partner lane = tcol ^ 8, same warp) + store
#pragma unroll
    for (int i = 0; i < 8; i++)
#pragma unroll
        for (int d = 0; d < 8; d++)
            o[i][d] += __shfl_xor_sync(0xffffffffu, o[i][d], 8);

    if ((tcol & 8) == 0) {
#pragma unroll
        for (int i = 0; i < 8; i++) {
            const float inv = __fdividef(1.f, l[i]);
            const int row = qt * BM + r0 + i;
            float4 oa, ob;
            oa.x = o[i][0] * inv; oa.y = o[i][1] * inv;
            oa.z = o[i][2] * inv; oa.w = o[i][3] * inv;
            ob.x = o[i][4] * inv; ob.y = o[i][5] * inv;
            ob.z = o[i][6] * inv; ob.w = o[i][7] * inv;
            float4* op = (float4*)(out + base + (size_t)row * HDIM + dmb);
            op[0] = oa;
            op[1] = ob;
        }
    }
}

extern "C" void kernel_launch(void* const* d_in, const int* in_sizes, int n_in,
                              void* d_out, int out_size) {
    const float* x  = (const float*)d_in[0];
    const float* Wq = (const float*)d_in[1];
    const float* Wk = (const float*)d_in[2];
    const float* Wv = (const float*)d_in[3];
    float* out = (float*)d_out;

    // idempotent; first harness call happens outside graph capture
    cudaFuncSetAttribute(flash_fwd, cudaFuncAttributeMaxDynamicSharedMemorySize, SMEM_BYTES);

    qkv_proj<<<(BATCH * SEQ) / 32, 192>>>(x, Wq, Wk, Wv);
    flash_fwd<<<BATCH * NTQ, 256, SMEM_BYTES>>>(out);
}

// round 11
// speedup vs baseline: 3.0960x; 3.0960x over previous
#include <cuda_runtime.h>
#include <cstdint>

#define BATCH 4
#define SEQ   4096
#define EMB   384
#define HDIM  64
#define BM    128
#define BN    128
#define NTQ   (SEQ / BM)          // 32
#define KST   68                  // K/V/Q row stride (floats)
#define PST   132                 // P row stride (floats)

// smem layout (float offsets): K double buf, V double buf, P (also Q staging)
#define KS_OFF 0                              // 2*128*68 = 17408
#define VS_OFF (2 * BN * KST)                 // 17408
#define PS_OFF (4 * BN * KST)                 // 34816
#define SMEM_FLOATS (PS_OFF + BM * PST)       // 51712
#define SMEM_BYTES  (SMEM_FLOATS * 4)         // 206848

__device__ float g_q[BATCH * SEQ * HDIM];
__device__ float g_k[BATCH * SEQ * HDIM];
__device__ float g_v[BATCH * SEQ * HDIM];

__device__ __forceinline__ void cp16(unsigned int saddr, const void* gptr) {
    asm volatile("cp.async.cg.shared.global [%0], [%1], 16;" :: "r"(saddr), "l"(gptr));
}
__device__ __forceinline__ void cp_commit() {
    asm volatile("cp.async.commit_group;");
}
__device__ __forceinline__ void mma_tf32(float& c0, float& c1, float& c2, float& c3,
                                         unsigned a0, unsigned a1, unsigned a2, unsigned a3,
                                         unsigned b0, unsigned b1) {
    asm volatile("mma.sync.aligned.m16n8k8.row.col.f32.tf32.tf32.f32 "
                 "{%0,%1,%2,%3}, {%4,%5,%6,%7}, {%8,%9}, {%0,%1,%2,%3};"
                 : "+f"(c0), "+f"(c1), "+f"(c2), "+f"(c3)
                 : "r"(a0), "r"(a1), "r"(a2), "r"(a3), "r"(b0), "r"(b1));
}
__device__ __forceinline__ unsigned f2tf32(float x) {
    unsigned r; asm("cvt.rna.tf32.f32 %0, %1;" : "=r"(r) : "f"(x)); return r;
}

// ---------------- fused QKV projection (R7 version, 16 rows/block) ----------------
__global__ __launch_bounds__(192) void qkv_proj(const float* __restrict__ x,
                                                const float* __restrict__ Wq,
                                                const float* __restrict__ Wk,
                                                const float* __restrict__ Wv) {
    __shared__ float4 xs4[16 * 96];
    const int tid = threadIdx.x;
    const size_t row0 = (size_t)blockIdx.x * 16;

    const float4* xsrc = (const float4*)(x + row0 * EMB);
#pragma unroll
    for (int i = 0; i < 8; i++) xs4[tid + i * 192] = xsrc[tid + i * 192];
    __syncthreads();

    const int mat = tid >> 6;
    const int col = tid & 63;
    const float* W = (mat == 0) ? Wq : (mat == 1 ? Wk : Wv);
    float* dst     = (mat == 0) ? g_q : (mat == 1 ? g_k : g_v);

    float acc[16];
#pragma unroll
    for (int r = 0; r < 16; r++) acc[r] = 0.f;

#pragma unroll 4
    for (int e4 = 0; e4 < 96; e4++) {
        const float w0 = W[(e4 * 4 + 0) * HDIM + col];
        const float w1 = W[(e4 * 4 + 1) * HDIM + col];
        const float w2 = W[(e4 * 4 + 2) * HDIM + col];
        const float w3 = W[(e4 * 4 + 3) * HDIM + col];
#pragma unroll
        for (int r = 0; r < 16; r++) {
            const float4 xv = xs4[r * 96 + e4];
            acc[r] = fmaf(xv.x, w0, fmaf(xv.y, w1, fmaf(xv.z, w2, fmaf(xv.w, w3, acc[r]))));
        }
    }
#pragma unroll
    for (int r = 0; r < 16; r++)
        dst[(row0 + r) * HDIM + col] = acc[r];
}

// ---------------- causal flash attention, tf32 mma.sync ----------------
// 256 threads = 8 warps; warp w owns rows 16w..16w+16 of the 128-row q tile.
// S: 16 n-tiles (m16n8k8) over BN=128, k = 8 steps over HDIM=64; Q as reg A-frags.
// P through shared (warp-private rows); PV: 16 s-chunks x 8 d-tiles.
__global__ __launch_bounds__(256, 1) void flash_fwd(float* __restrict__ out) {
    extern __shared__ float sm[];
    const int tid  = threadIdx.x;
    const int warp = tid >> 5;
    const int lane = tid & 31;
    const int grp  = lane >> 2;    // 0..7
    const int qd   = lane & 3;     // 0..3
    const int b    = blockIdx.x & 3;
    const int qt   = blockIdx.x >> 2;
    const float NEG_INF = __int_as_float(0xff800000);
    const size_t base = (size_t)b * SEQ * HDIM;
    const unsigned int smb = (unsigned int)__cvta_generic_to_shared(sm);
    const int nkt = qt + 1;
    const int rl = warp * 16 + grp;     // local row (lo), +8 = hi

    // ---- stage Q (scaled 1/8) into P region, then load A-fragments ----
    {
        const float4* qsrc = (const float4*)(g_q + base + (size_t)qt * BM * HDIM);
#pragma unroll
        for (int j = 0; j < 8; j++) {
            const int idx = tid + 256 * j;       // 0..2047
            const int row = idx >> 4, c4 = idx & 15;
            float4 v = qsrc[idx];
            v.x *= 0.125f; v.y *= 0.125f; v.z *= 0.125f; v.w *= 0.125f;
            *(float4*)&sm[PS_OFF + row * KST + c4 * 4] = v;
        }
    }
    __syncthreads();
    unsigned qa[8][4];
#pragma unroll
    for (int kk = 0; kk < 8; kk++) {
        qa[kk][0] = f2tf32(sm[PS_OFF + rl * KST + kk * 8 + qd]);
        qa[kk][1] = f2tf32(sm[PS_OFF + (rl + 8) * KST + kk * 8 + qd]);
        qa[kk][2] = f2tf32(sm[PS_OFF + rl * KST + kk * 8 + qd + 4]);
        qa[kk][3] = f2tf32(sm[PS_OFF + (rl + 8) * KST + kk * 8 + qd + 4]);
    }
    __syncthreads();   // Q staging done; P region free

    float o[8][4];
#pragma unroll
    for (int t = 0; t < 8; t++)
#pragma unroll
        for (int e = 0; e < 4; e++) o[t][e] = 0.f;
    float m_lo = NEG_INF, m_hi = NEG_INF, l_lo = 0.f, l_hi = 0.f;

    // prologue: K0 + V0 in one cp.async group
    {
        const float* kg = g_k + base;
        const float* vg = g_v + base;
#pragma unroll
        for (int j = 0; j < 8; j++) {
            const int idx = tid + 256 * j;
            const int row = idx >> 4, c4 = idx & 15;
            cp16(smb + (unsigned int)((KS_OFF + row * KST + c4 * 4) << 2), kg + idx * 4);
            cp16(smb + (unsigned int)((VS_OFF + row * KST + c4 * 4) << 2), vg + idx * 4);
        }
        cp_commit();
    }

    for (int kt = 0; kt < nkt; kt++) {
        const int cur = kt & 1;
        __syncthreads();   // stage cur^1 free (consumed two iters ago)

        if (kt + 1 < nkt) {
            const int ns = cur ^ 1;
            const float* kg = g_k + base + (size_t)(kt + 1) * BN * HDIM;
            const float* vg = g_v + base + (size_t)(kt + 1) * BN * HDIM;
#pragma unroll
            for (int j = 0; j < 8; j++) {
                const int idx = tid + 256 * j;
                const int row = idx >> 4, c4 = idx & 15;
                cp16(smb + (unsigned int)((KS_OFF + (ns * BN + row) * KST + c4 * 4) << 2), kg + idx * 4);
                cp16(smb + (unsigned int)((VS_OFF + (ns * BN + row) * KST + c4 * 4) << 2), vg + idx * 4);
            }
            cp_commit();
            asm volatile("cp.async.wait_group 1;");
        } else {
            asm volatile("cp.async.wait_group 0;");
        }
        __syncthreads();

        // ---- S = Q K^T : 16 n-tiles, 8 k-steps ----
        float c[16][4];
#pragma unroll
        for (int nt = 0; nt < 16; nt++)
#pragma unroll
            for (int e = 0; e < 4; e++) c[nt][e] = 0.f;

        const float* Kst = sm + KS_OFF + cur * BN * KST;
#pragma unroll
        for (int kk = 0; kk < 8; kk++) {
#pragma unroll
            for (int nt = 0; nt < 16; nt++) {
                const unsigned b0 = __float_as_uint(Kst[(nt * 8 + grp) * KST + kk * 8 + qd]);
                const unsigned b1 = __float_as_uint(Kst[(nt * 8 + grp) * KST + kk * 8 + qd + 4]);
                mma_tf32(c[nt][0], c[nt][1], c[nt][2], c[nt][3],
                         qa[kk][0], qa[kk][1], qa[kk][2], qa[kk][3], b0, b1);
            }
        }

        if (kt == qt) {   // diagonal tile: causal mask
            const int grow_lo = qt * BM + rl;
            const int grow_hi = grow_lo + 8;
#pragma unroll
            for (int nt = 0; nt < 16; nt++) {
                const int col = kt * BN + nt * 8 + 2 * qd;
                if (col     > grow_lo) c[nt][0] = NEG_INF;
                if (col + 1 > grow_lo) c[nt][1] = NEG_INF;
                if (col     > grow_hi) c[nt][2] = NEG_INF;
                if (col + 1 > grow_hi) c[nt][3] = NEG_INF;
            }
        }

        // ---- online softmax (quad reduce over lanes qd=0..3) ----
        float tlo = NEG_INF, thi = NEG_INF;
#pragma unroll
        for (int nt = 0; nt < 16; nt++) {
            tlo = fmaxf(tlo, fmaxf(c[nt][0], c[nt][1]));
            thi = fmaxf(thi, fmaxf(c[nt][2], c[nt][3]));
        }
        tlo = fmaxf(tlo, __shfl_xor_sync(0xffffffffu, tlo, 1));
        tlo = fmaxf(tlo, __shfl_xor_sync(0xffffffffu, tlo, 2));
        thi = fmaxf(thi, __shfl_xor_sync(0xffffffffu, thi, 1));
        thi = fmaxf(thi, __shfl_xor_sync(0xffffffffu, thi, 2));
        const float mn_lo = fmaxf(m_lo, tlo);
        const float mn_hi = fmaxf(m_hi, thi);
        const float al_lo = __expf(m_lo - mn_lo);
        const float al_hi = __expf(m_hi - mn_hi);
        float s_lo = 0.f, s_hi = 0.f;
#pragma unroll
        for (int nt = 0; nt < 16; nt++) {
            c[nt][0] = __expf(c[nt][0] - mn_lo);
            c[nt][1] = __expf(c[nt][1] - mn_lo);
            c[nt][2] = __expf(c[nt][2] - mn_hi);
            c[nt][3] = __expf(c[nt][3] - mn_hi);
            s_lo += c[nt][0] + c[nt][1];
            s_hi += c[nt][2] + c[nt][3];
        }
        s_lo += __shfl_xor_sync(0xffffffffu, s_lo, 1);
        s_lo += __shfl_xor_sync(0xffffffffu, s_lo, 2);
        s_hi += __shfl_xor_sync(0xffffffffu, s_hi, 1);
        s_hi += __shfl_xor_sync(0xffffffffu, s_hi, 2);
        l_lo = l_lo * al_lo + s_lo;  m_lo = mn_lo;
        l_hi = l_hi * al_hi + s_hi;  m_hi = mn_hi;
#pragma unroll
        for (int t = 0; t < 8; t++) {
            o[t][0] *= al_lo; o[t][1] *= al_lo;
            o[t][2] *= al_hi; o[t][3] *= al_hi;
        }

        // ---- write P (warp-private rows) ----
#pragma unroll
        for (int nt = 0; nt < 16; nt++) {
            *(float2*)&sm[PS_OFF + rl * PST + nt * 8 + 2 * qd]       = make_float2(c[nt][0], c[nt][1]);
            *(float2*)&sm[PS_OFF + (rl + 8) * PST + nt * 8 + 2 * qd] = make_float2(c[nt][2], c[nt][3]);
        }
        __syncwarp();

        // ---- O += P V : 16 s-chunks, 8 d-tiles ----
        const float* Vst = sm + VS_OFF + cur * BN * KST;
#pragma unroll
        for (int sc = 0; sc < 16; sc++) {
            const unsigned a0 = f2tf32(sm[PS_OFF + rl * PST + sc * 8 + qd]);
            const unsigned a1 = f2tf32(sm[PS_OFF + (rl + 8) * PST + sc * 8 + qd]);
            const unsigned a2 = f2tf32(sm[PS_OFF + rl * PST + sc * 8 + qd + 4]);
            const unsigned a3 = f2tf32(sm[PS_OFF + (rl + 8) * PST + sc * 8 + qd + 4]);
#pragma unroll
            for (int t = 0; t < 8; t++) {
                const unsigned b0 = __float_as_uint(Vst[(sc * 8 + qd) * KST + t * 8 + grp]);
                const unsigned b1 = __float_as_uint(Vst[(sc * 8 + qd + 4) * KST + t * 8 + grp]);
                mma_tf32(o[t][0], o[t][1], o[t][2], o[t][3], a0, a1, a2, a3, b0, b1);
            }
        }
    }

    // ---- epilogue ----
    const float inv_lo = __fdividef(1.f, l_lo);
    const float inv_hi = __fdividef(1.f, l_hi);
    const int grow_lo = qt * BM + rl;
#pragma unroll
    for (int t = 0; t < 8; t++) {
        *(float2*)(out + base + (size_t)grow_lo * HDIM + t * 8 + 2 * qd) =
            make_float2(o[t][0] * inv_lo, o[t][1] * inv_lo);
        *(float2*)(out + base + (size_t)(grow_lo + 8) * HDIM + t * 8 + 2 * qd) =
            make_float2(o[t][2] * inv_hi, o[t][3] * inv_hi);
    }
}

extern "C" void kernel_launch(void* const* d_in, const int* in_sizes, int n_in,
                              void* d_out, int out_size) {
    const float* x  = (const float*)d_in[0];
    const float* Wq = (const float*)d_in[1];
    const float* Wk = (const float*)d_in[2];
    const float* Wv = (const float*)d_in[3];
    float* out = (float*)d_out;

    cudaFuncSetAttribute(flash_fwd, cudaFuncAttributeMaxDynamicSharedMemorySize, SMEM_BYTES);

    qkv_proj<<<(BATCH * SEQ) / 16, 192>>>(x, Wq, Wk, Wv);
    flash_fwd<<<BATCH * NTQ, 256, SMEM_BYTES>>>(out);
}

// round 13
// speedup vs baseline: 4.5147x; 1.4582x over previous
#include <cuda_runtime.h>
#include <cstdint>

#define BATCH 4
#define SEQ   4096
#define EMB   384
#define HDIM  64
#define BM    64
#define BN    64
#define KST   68                  // K / P / Q stride (4*grp+qd banks, conflict-free)
#define VST   72                  // V stride (8*qd+grp banks, conflict-free)
#define NCHUNK_MAX 4

// smem (float offsets)
#define KS_OFF 0                              // 64*68 = 4352
#define VS_OFF (BN * KST)                     // 4352; V: 64*72 = 4608
#define PS_OFF (VS_OFF + BN * VST)            // 8960; P/Q: 64*68 = 4352
#define SMEM_FLOATS (PS_OFF + BM * KST)       // 13312
#define SMEM_BYTES  (SMEM_FLOATS * 4)         // 53248

__device__ float g_q[BATCH * SEQ * HDIM];
__device__ float g_k[BATCH * SEQ * HDIM];
__device__ float g_v[BATCH * SEQ * HDIM];
__device__ float g_op[NCHUNK_MAX][BATCH * SEQ * HDIM];   // unnormalized partial O
__device__ float g_pm[NCHUNK_MAX][BATCH * SEQ];          // partial running max
__device__ float g_pl[NCHUNK_MAX][BATCH * SEQ];          // partial running sum

__device__ __forceinline__ void cp16(unsigned int saddr, const void* gptr) {
    asm volatile("cp.async.cg.shared.global [%0], [%1], 16;" :: "r"(saddr), "l"(gptr));
}
__device__ __forceinline__ void mma_tf32(float& c0, float& c1, float& c2, float& c3,
                                         unsigned a0, unsigned a1, unsigned a2, unsigned a3,
                                         unsigned b0, unsigned b1) {
    asm volatile("mma.sync.aligned.m16n8k8.row.col.f32.tf32.tf32.f32 "
                 "{%0,%1,%2,%3}, {%4,%5,%6,%7}, {%8,%9}, {%0,%1,%2,%3};"
                 : "+f"(c0), "+f"(c1), "+f"(c2), "+f"(c3)
                 : "r"(a0), "r"(a1), "r"(a2), "r"(a3), "r"(b0), "r"(b1));
}
__device__ __forceinline__ unsigned f2tf32(float x) {
    unsigned r; asm("cvt.rna.tf32.f32 %0, %1;" : "=r"(r) : "f"(x)); return r;
}

// ---------------- fused QKV projection (unchanged) ----------------
__global__ __launch_bounds__(192) void qkv_proj(const float* __restrict__ x,
                                                const float* __restrict__ Wq,
                                                const float* __restrict__ Wk,
                                                const float* __restrict__ Wv) {
    __shared__ float4 xs4[16 * 96];
    const int tid = threadIdx.x;
    const size_t row0 = (size_t)blockIdx.x * 16;

    const float4* xsrc = (const float4*)(x + row0 * EMB);
#pragma unroll
    for (int i = 0; i < 8; i++) xs4[tid + i * 192] = xsrc[tid + i * 192];
    __syncthreads();

    const int mat = tid >> 6;
    const int col = tid & 63;
    const float* W = (mat == 0) ? Wq : (mat == 1 ? Wk : Wv);
    float* dst     = (mat == 0) ? g_q : (mat == 1 ? g_k : g_v);

    float acc[16];
#pragma unroll
    for (int r = 0; r < 16; r++) acc[r] = 0.f;

#pragma unroll 4
    for (int e4 = 0; e4 < 96; e4++) {
        const float w0 = W[(e4 * 4 + 0) * HDIM + col];
        const float w1 = W[(e4 * 4 + 1) * HDIM + col];
        const float w2 = W[(e4 * 4 + 2) * HDIM + col];
        const float w3 = W[(e4 * 4 + 3) * HDIM + col];
#pragma unroll
        for (int r = 0; r < 16; r++) {
            const float4 xv = xs4[r * 96 + e4];
            acc[r] = fmaf(xv.x, w0, fmaf(xv.y, w1, fmaf(xv.z, w2, fmaf(xv.w, w3, acc[r]))));
        }
    }
#pragma unroll
    for (int r = 0; r < 16; r++)
        dst[(row0 + r) * HDIM + col] = acc[r];
}

// ---------------- tf32 flash, BM=64 x BN=64, split-KV chunks of 16 tiles ----------------
// 128 threads = 4 warps; warp owns rows 16w..16w+16. Chunk writes partial (O, m, l).
__global__ __launch_bounds__(128, 4) void flash_fwd() {
    extern __shared__ float sm[];
    const int tid  = threadIdx.x;
    const int warp = tid >> 5;
    const int lane = tid & 31;
    const int grp  = lane >> 2;
    const int qd   = lane & 3;
    const int b    = blockIdx.x & 3;
    const int w    = 159 - (blockIdx.x >> 2);   // heavy chunks first
    const float NEG_INF = __int_as_float(0xff800000);
    const size_t base = (size_t)b * SEQ * HDIM;
    const unsigned int smb = (unsigned int)__cvta_generic_to_shared(sm);

    // decode (qt, chunk) from w: w = sum_{q<qt} ceil((q+1)/16) + chunk
    int qt = 0, rem = w;
    for (; qt < 64; qt++) {
        const int c = (qt + 16) >> 4;
        if (rem < c) break;
        rem -= c;
    }
    const int lo = rem * 16;
    const int nkt = qt + 1;
    const int hi = (lo + 16 < nkt) ? lo + 16 : nkt;
    const int rl = warp * 16 + grp;

    // stage Q (scaled 1/8) into P region, extract A-fragments
    {
        const float4* qsrc = (const float4*)(g_q + base + (size_t)qt * BM * HDIM);
#pragma unroll
        for (int j = 0; j < 8; j++) {
            const int idx = tid + 128 * j;     // 0..1023
            const int row = idx >> 4, c4 = idx & 15;
            float4 v = qsrc[idx];
            v.x *= 0.125f; v.y *= 0.125f; v.z *= 0.125f; v.w *= 0.125f;
            *(float4*)&sm[PS_OFF + row * KST + c4 * 4] = v;
        }
    }
    __syncthreads();
    unsigned qa[8][4];
#pragma unroll
    for (int kk = 0; kk < 8; kk++) {
        qa[kk][0] = f2tf32(sm[PS_OFF + rl * KST + kk * 8 + qd]);
        qa[kk][1] = f2tf32(sm[PS_OFF + (rl + 8) * KST + kk * 8 + qd]);
        qa[kk][2] = f2tf32(sm[PS_OFF + rl * KST + kk * 8 + qd + 4]);
        qa[kk][3] = f2tf32(sm[PS_OFF + (rl + 8) * KST + kk * 8 + qd + 4]);
    }

    float o[8][4];
#pragma unroll
    for (int t = 0; t < 8; t++)
#pragma unroll
        for (int e = 0; e < 4; e++) o[t][e] = 0.f;
    float m_lo = NEG_INF, m_hi = NEG_INF, l_lo = 0.f, l_hi = 0.f;

    for (int kt = lo; kt < hi; kt++) {
        __syncthreads();   // P/Q consumed, K/V buffers free
        {
            const float* kg = g_k + base + (size_t)kt * BN * HDIM;
            const float* vg = g_v + base + (size_t)kt * BN * HDIM;
#pragma unroll
            for (int j = 0; j < 8; j++) {
                const int idx = tid + 128 * j;   // 0..1023
                const int row = idx >> 4, c4 = idx & 15;
                cp16(smb + (unsigned int)((KS_OFF + row * KST + c4 * 4) << 2), kg + idx * 4);
                cp16(smb + (unsigned int)((VS_OFF + row * VST + c4 * 4) << 2), vg + idx * 4);
            }
            asm volatile("cp.async.commit_group;");
            asm volatile("cp.async.wait_group 0;");
        }
        __syncthreads();

        // ---- S = Q K^T : 8 n-tiles, 8 k-steps ----
        float c[8][4];
#pragma unroll
        for (int nt = 0; nt < 8; nt++)
#pragma unroll
            for (int e = 0; e < 4; e++) c[nt][e] = 0.f;

#pragma unroll
        for (int kk = 0; kk < 8; kk++) {
#pragma unroll
            for (int nt = 0; nt < 8; nt++) {
                const unsigned b0 = __float_as_uint(sm[KS_OFF + (nt * 8 + grp) * KST + kk * 8 + qd]);
                const unsigned b1 = __float_as_uint(sm[KS_OFF + (nt * 8 + grp) * KST + kk * 8 + qd + 4]);
                mma_tf32(c[nt][0], c[nt][1], c[nt][2], c[nt][3],
                         qa[kk][0], qa[kk][1], qa[kk][2], qa[kk][3], b0, b1);
            }
        }

        if (kt == qt) {   // diagonal tile: causal mask
            const int grow_lo = qt * BM + rl;
            const int grow_hi = grow_lo + 8;
#pragma unroll
            for (int nt = 0; nt < 8; nt++) {
                const int col = kt * BN + nt * 8 + 2 * qd;
                if (col     > grow_lo) c[nt][0] = NEG_INF;
                if (col + 1 > grow_lo) c[nt][1] = NEG_INF;
                if (col     > grow_hi) c[nt][2] = NEG_INF;
                if (col + 1 > grow_hi) c[nt][3] = NEG_INF;
            }
        }

        // ---- online softmax (quad reduce) ----
        float tlo = NEG_INF, thi = NEG_INF;
#pragma unroll
        for (int nt = 0; nt < 8; nt++) {
            tlo = fmaxf(tlo, fmaxf(c[nt][0], c[nt][1]));
            thi = fmaxf(thi, fmaxf(c[nt][2], c[nt][3]));
        }
        tlo = fmaxf(tlo, __shfl_xor_sync(0xffffffffu, tlo, 1));
        tlo = fmaxf(tlo, __shfl_xor_sync(0xffffffffu, tlo, 2));
        thi = fmaxf(thi, __shfl_xor_sync(0xffffffffu, thi, 1));
        thi = fmaxf(thi, __shfl_xor_sync(0xffffffffu, thi, 2));
        const float mn_lo = fmaxf(m_lo, tlo);
        const float mn_hi = fmaxf(m_hi, thi);
        const float al_lo = __expf(m_lo - mn_lo);
        const float al_hi = __expf(m_hi - mn_hi);
        float s_lo = 0.f, s_hi = 0.f;
#pragma unroll
        for (int nt = 0; nt < 8; nt++) {
            c[nt][0] = __expf(c[nt][0] - mn_lo);
            c[nt][1] = __expf(c[nt][1] - mn_lo);
            c[nt][2] = __expf(c[nt][2] - mn_hi);
            c[nt][3] = __expf(c[nt][3] - mn_hi);
            s_lo += c[nt][0] + c[nt][1];
            s_hi += c[nt][2] + c[nt][3];
        }
        s_lo += __shfl_xor_sync(0xffffffffu, s_lo, 1);
        s_lo += __shfl_xor_sync(0xffffffffu, s_lo, 2);
        s_hi += __shfl_xor_sync(0xffffffffu, s_hi, 1);
        s_hi += __shfl_xor_sync(0xffffffffu, s_hi, 2);
        l_lo = l_lo * al_lo + s_lo;  m_lo = mn_lo;
        l_hi = l_hi * al_hi + s_hi;  m_hi = mn_hi;
#pragma unroll
        for (int t = 0; t < 8; t++) {
            o[t][0] *= al_lo; o[t][1] *= al_lo;
            o[t][2] *= al_hi; o[t][3] *= al_hi;
        }

        // ---- write P (warp-private rows) ----
#pragma unroll
        for (int nt = 0; nt < 8; nt++) {
            *(float2*)&sm[PS_OFF + rl * KST + nt * 8 + 2 * qd]       = make_float2(c[nt][0], c[nt][1]);
            *(float2*)&sm[PS_OFF + (rl + 8) * KST + nt * 8 + 2 * qd] = make_float2(c[nt][2], c[nt][3]);
        }
        __syncwarp();

        // ---- O += P V : 8 s-chunks, 8 d-tiles ----
#pragma unroll
        for (int sc = 0; sc < 8; sc++) {
            const unsigned a0 = f2tf32(sm[PS_OFF + rl * KST + sc * 8 + qd]);
            const unsigned a1 = f2tf32(sm[PS_OFF + (rl + 8) * KST + sc * 8 + qd]);
            const unsigned a2 = f2tf32(sm[PS_OFF + rl * KST + sc * 8 + qd + 4]);
            const unsigned a3 = f2tf32(sm[PS_OFF + (rl + 8) * KST + sc * 8 + qd + 4]);
#pragma unroll
            for (int t = 0; t < 8; t++) {
                const unsigned b0 = __float_as_uint(sm[VS_OFF + (sc * 8 + qd) * VST + t * 8 + grp]);
                const unsigned b1 = __float_as_uint(sm[VS_OFF + (sc * 8 + qd + 4) * VST + t * 8 + grp]);
                mma_tf32(o[t][0], o[t][1], o[t][2], o[t][3], a0, a1, a2, a3, b0, b1);
            }
        }
    }

    // ---- epilogue: write UNNORMALIZED partials ----
    const int chunk = rem;
    const int grow_lo = qt * BM + rl;
    float* op = g_op[chunk] + (size_t)b * SEQ * HDIM;
#pragma unroll
    for (int t = 0; t < 8; t++) {
        *(float2*)(op + (size_t)grow_lo * HDIM + t * 8 + 2 * qd) = make_float2(o[t][0], o[t][1]);
        *(float2*)(op + (size_t)(grow_lo + 8) * HDIM + t * 8 + 2 * qd) = make_float2(o[t][2], o[t][3]);
    }
    if (qd == 0) {
        g_pm[chunk][b * SEQ + grow_lo] = m_lo;
        g_pl[chunk][b * SEQ + grow_lo] = l_lo;
        g_pm[chunk][b * SEQ + grow_lo + 8] = m_hi;
        g_pl[chunk][b * SEQ + grow_lo + 8] = l_hi;
    }
}

// ---------------- merge partials ----------------
// thread g: row = g>>2, dims [(g&3)*16, +16)
__global__ __launch_bounds__(256) void merge_partials(float* __restrict__ out) {
    const int g   = blockIdx.x * 256 + threadIdx.x;
    const int row = g >> 2;                 // 0..16383 (b*SEQ + t)
    const int d0  = (g & 3) * 16;
    const int t   = row & (SEQ - 1);
    const int qt  = t >> 6;
    const int nc  = (qt + 16) >> 4;         // ceil((qt+1)/16)

    float mx = __int_as_float(0xff800000);
#pragma unroll
    for (int c = 0; c < NCHUNK_MAX; c++)
        if (c < nc) mx = fmaxf(mx, g_pm[c][row]);

    float w[NCHUNK_MAX];
    float L = 0.f;
#pragma unroll
    for (int c = 0; c < NCHUNK_MAX; c++) {
        w[c] = (c < nc) ? __expf(g_pm[c][row] - mx) : 0.f;
        if (c < nc) L += w[c] * g_pl[c][row];
    }
    const float inv = __fdividef(1.f, L);

#pragma unroll
    for (int v = 0; v < 4; v++) {
        float4 acc = make_float4(0.f, 0.f, 0.f, 0.f);
#pragma unroll
        for (int c = 0; c < NCHUNK_MAX; c++) {
            if (c < nc) {
                const float4 p = *(const float4*)(g_op[c] + (size_t)row * HDIM + d0 + v * 4);
                acc.x = fmaf(w[c], p.x, acc.x);
                acc.y = fmaf(w[c], p.y, acc.y);
                acc.z = fmaf(w[c], p.z, acc.z);
                acc.w = fmaf(w[c], p.w, acc.w);
            }
        }
        acc.x *= inv; acc.y *= inv; acc.z *= inv; acc.w *= inv;
        *(float4*)(out + (size_t)row * HDIM + d0 + v * 4) = acc;
    }
}

extern "C" void kernel_launch(void* const* d_in, const int* in_sizes, int n_in,
                              void* d_out, int out_size) {
    const float* x  = (const float*)d_in[0];
    const float* Wq = (const float*)d_in[1];
    const float* Wk = (const float*)d_in[2];
    const float* Wv = (const float*)d_in[3];
    float* out = (float*)d_out;

    cudaFuncSetAttribute(flash_fwd, cudaFuncAttributeMaxDynamicSharedMemorySize, SMEM_BYTES);

    qkv_proj<<<(BATCH * SEQ) / 16, 192>>>(x, Wq, Wk, Wv);
    flash_fwd<<<BATCH * 160, 128, SMEM_BYTES>>>();
    merge_partials<<<BATCH * SEQ * 4 / 256, 256>>>(out);
}

// round 17
// speedup vs baseline: 8.0029x; 1.7726x over previous
#include <cuda_runtime.h>
#include <cstdint>

#define BATCH 4
#define SEQ   4096
#define EMB   384
#define HDIM  64
#define BM    64
#define BN    64
#define KST   68                  // K / P / Q stride (conflict-free)
#define VST   72                  // V stride (conflict-free)
#define NCHUNK_MAX 4

// flash smem (float offsets)
#define KS_OFF 0
#define VS_OFF (BN * KST)
#define PS_OFF (VS_OFF + BN * VST)
#define SMEM_FLOATS (PS_OFF + BM * KST)
#define SMEM_BYTES  (SMEM_FLOATS * 4)         // 53248

// qkv_mma smem (float offsets): x double buf (128x68), W double buf (64x72)
#define XST 68
#define WST 72
#define XO  0
#define WO  (2 * 128 * XST)
#define QKV_SMEM_FLOATS (WO + 2 * 64 * WST)    // 26624
#define QKV_SMEM_BYTES  (QKV_SMEM_FLOATS * 4)  // 106496

__device__ float g_q[BATCH * SEQ * HDIM];
__device__ float g_k[BATCH * SEQ * HDIM];
__device__ float g_v[BATCH * SEQ * HDIM];
__device__ float g_op[NCHUNK_MAX][BATCH * SEQ * HDIM];
__device__ float g_pm[NCHUNK_MAX][BATCH * SEQ];
__device__ float g_pl[NCHUNK_MAX][BATCH * SEQ];

__device__ __forceinline__ void cp16(unsigned int saddr, const void* gptr) {
    asm volatile("cp.async.cg.shared.global [%0], [%1], 16;" :: "r"(saddr), "l"(gptr));
}
__device__ __forceinline__ void mma_tf32(float& c0, float& c1, float& c2, float& c3,
                                         unsigned a0, unsigned a1, unsigned a2, unsigned a3,
                                         unsigned b0, unsigned b1) {
    asm volatile("mma.sync.aligned.m16n8k8.row.col.f32.tf32.tf32.f32 "
                 "{%0,%1,%2,%3}, {%4,%5,%6,%7}, {%8,%9}, {%0,%1,%2,%3};"
                 : "+f"(c0), "+f"(c1), "+f"(c2), "+f"(c3)
                 : "r"(a0), "r"(a1), "r"(a2), "r"(a3), "r"(b0), "r"(b1));
}
__device__ __forceinline__ unsigned f2tf32(float x) {
    unsigned r; asm("cvt.rna.tf32.f32 %0, %1;" : "=r"(r) : "f"(x)); return r;
}

// ---------------- QKV projection via tf32 mma (A and B both rna-rounded) ----------------
__global__ __launch_bounds__(256, 2) void qkv_mma(const float* __restrict__ x,
                                                  const float* __restrict__ Wq,
                                                  const float* __restrict__ Wk,
                                                  const float* __restrict__ Wv) {
    extern __shared__ float sm[];
    const int tid  = threadIdx.x;
    const int warp = tid >> 5;
    const int lane = tid & 31;
    const int g8   = lane >> 2;    // 0..7
    const int qd   = lane & 3;     // 0..3
    const int rb   = blockIdx.x / 3;
    const int mat  = blockIdx.x - 3 * rb;
    const float* W = (mat == 0) ? Wq : (mat == 1 ? Wk : Wv);
    float* dst     = (mat == 0) ? g_q : (mat == 1 ? g_k : g_v);
    const size_t row0 = (size_t)rb * 128;
    const int rl = warp * 16 + g8;
    const unsigned int smb = (unsigned int)__cvta_generic_to_shared(sm);

    float c[8][4];
#pragma unroll
    for (int nt = 0; nt < 8; nt++)
#pragma unroll
        for (int e = 0; e < 4; e++) c[nt][e] = 0.f;

    // stage chunk 0
    {
        const float* xs = x + row0 * EMB;
#pragma unroll
        for (int j = 0; j < 8; j++) {
            const int idx = tid + 256 * j;
            const int row = idx >> 4, c4 = idx & 15;
            cp16(smb + (unsigned int)((XO + row * XST + c4 * 4) << 2),
                 xs + (size_t)row * EMB + c4 * 4);
        }
#pragma unroll
        for (int j = 0; j < 4; j++) {
            const int idx = tid + 256 * j;
            const int row = idx >> 4, c4 = idx & 15;
            cp16(smb + (unsigned int)((WO + row * WST + c4 * 4) << 2),
                 W + (size_t)row * HDIM + c4 * 4);
        }
        asm volatile("cp.async.commit_group;");
    }

    for (int ch = 0; ch < 6; ch++) {
        const int cur = ch & 1;
        __syncthreads();

        if (ch + 1 < 6) {
            const int ns = cur ^ 1;
            const float* xs = x + row0 * EMB + (ch + 1) * 64;
            const float* ws = W + (size_t)(ch + 1) * 64 * HDIM;
#pragma unroll
            for (int j = 0; j < 8; j++) {
                const int idx = tid + 256 * j;
                const int row = idx >> 4, c4 = idx & 15;
                cp16(smb + (unsigned int)((XO + (ns * 128 + row) * XST + c4 * 4) << 2),
                     xs + (size_t)row * EMB + c4 * 4);
            }
#pragma unroll
            for (int j = 0; j < 4; j++) {
                const int idx = tid + 256 * j;
                const int row = idx >> 4, c4 = idx & 15;
                cp16(smb + (unsigned int)((WO + (ns * 64 + row) * WST + c4 * 4) << 2),
                     ws + (size_t)row * HDIM + c4 * 4);
            }
            asm volatile("cp.async.commit_group;");
            asm volatile("cp.async.wait_group 1;");
        } else {
            asm volatile("cp.async.wait_group 0;");
        }
        __syncthreads();

        const float* Xs = sm + XO + cur * 128 * XST;
        const float* Ws = sm + WO + cur * 64 * WST;
#pragma unroll
        for (int kk = 0; kk < 8; kk++) {
            const unsigned a0 = f2tf32(Xs[rl * XST + kk * 8 + qd]);
            const unsigned a1 = f2tf32(Xs[(rl + 8) * XST + kk * 8 + qd]);
            const unsigned a2 = f2tf32(Xs[rl * XST + kk * 8 + qd + 4]);
            const unsigned a3 = f2tf32(Xs[(rl + 8) * XST + kk * 8 + qd + 4]);
#pragma unroll
            for (int nt = 0; nt < 8; nt++) {
                const unsigned b0 = f2tf32(Ws[(kk * 8 + qd) * WST + nt * 8 + g8]);       // rna, not truncate
                const unsigned b1 = f2tf32(Ws[(kk * 8 + qd + 4) * WST + nt * 8 + g8]);   // rna, not truncate
                mma_tf32(c[nt][0], c[nt][1], c[nt][2], c[nt][3], a0, a1, a2, a3, b0, b1);
            }
        }
    }

    const size_t gr = row0 + rl;
#pragma unroll
    for (int nt = 0; nt < 8; nt++) {
        *(float2*)(dst + gr * HDIM + nt * 8 + 2 * qd)       = make_float2(c[nt][0], c[nt][1]);
        *(float2*)(dst + (gr + 8) * HDIM + nt * 8 + 2 * qd) = make_float2(c[nt][2], c[nt][3]);
    }
}

// ---------------- tf32 flash, BM=64 x BN=64, split-KV chunks of 16 tiles ----------------
__global__ __launch_bounds__(128, 4) void flash_fwd() {
    extern __shared__ float sm[];
    const int tid  = threadIdx.x;
    const int warp = tid >> 5;
    const int lane = tid & 31;
    const int grp  = lane >> 2;
    const int qd   = lane & 3;
    const int b    = blockIdx.x & 3;
    const int w    = 159 - (blockIdx.x >> 2);   // heavy chunks first
    const float NEG_INF = __int_as_float(0xff800000);
    const size_t base = (size_t)b * SEQ * HDIM;
    const unsigned int smb = (unsigned int)__cvta_generic_to_shared(sm);

    int qt = 0, rem = w;
    for (; qt < 64; qt++) {
        const int c = (qt + 16) >> 4;
        if (rem < c) break;
        rem -= c;
    }
    const int lo = rem * 16;
    const int nkt = qt + 1;
    const int hi = (lo + 16 < nkt) ? lo + 16 : nkt;
    const int rl = warp * 16 + grp;

    {
        const float4* qsrc = (const float4*)(g_q + base + (size_t)qt * BM * HDIM);
#pragma unroll
        for (int j = 0; j < 8; j++) {
            const int idx = tid + 128 * j;
            const int row = idx >> 4, c4 = idx & 15;
            float4 v = qsrc[idx];
            v.x *= 0.125f; v.y *= 0.125f; v.z *= 0.125f; v.w *= 0.125f;
            *(float4*)&sm[PS_OFF + row * KST + c4 * 4] = v;
        }
    }
    __syncthreads();
    unsigned qa[8][4];
#pragma unroll
    for (int kk = 0; kk < 8; kk++) {
        qa[kk][0] = f2tf32(sm[PS_OFF + rl * KST + kk * 8 + qd]);
        qa[kk][1] = f2tf32(sm[PS_OFF + (rl + 8) * KST + kk * 8 + qd]);
        qa[kk][2] = f2tf32(sm[PS_OFF + rl * KST + kk * 8 + qd + 4]);
        qa[kk][3] = f2tf32(sm[PS_OFF + (rl + 8) * KST + kk * 8 + qd + 4]);
    }

    float o[8][4];
#pragma unroll
    for (int t = 0; t < 8; t++)
#pragma unroll
        for (int e = 0; e < 4; e++) o[t][e] = 0.f;
    float m_lo = NEG_INF, m_hi = NEG_INF, l_lo = 0.f, l_hi = 0.f;

    for (int kt = lo; kt < hi; kt++) {
        __syncthreads();
        {
            const float* kg = g_k + base + (size_t)kt * BN * HDIM;
            const float* vg = g_v + base + (size_t)kt * BN * HDIM;
#pragma unroll
            for (int j = 0; j < 8; j++) {
                const int idx = tid + 128 * j;
                const int row = idx >> 4, c4 = idx & 15;
                cp16(smb + (unsigned int)((KS_OFF + row * KST + c4 * 4) << 2), kg + idx * 4);
                cp16(smb + (unsigned int)((VS_OFF + row * VST + c4 * 4) << 2), vg + idx * 4);
            }
            asm volatile("cp.async.commit_group;");
            asm volatile("cp.async.wait_group 0;");
        }
        __syncthreads();

        float c[8][4];
#pragma unroll
        for (int nt = 0; nt < 8; nt++)
#pragma unroll
            for (int e = 0; e < 4; e++) c[nt][e] = 0.f;

#pragma unroll
        for (int kk = 0; kk < 8; kk++) {
#pragma unroll
            for (int nt = 0; nt < 8; nt++) {
                const unsigned b0 = __float_as_uint(sm[KS_OFF + (nt * 8 + grp) * KST + kk * 8 + qd]);
                const unsigned b1 = __float_as_uint(sm[KS_OFF + (nt * 8 + grp) * KST + kk * 8 + qd + 4]);
                mma_tf32(c[nt][0], c[nt][1], c[nt][2], c[nt][3],
                         qa[kk][0], qa[kk][1], qa[kk][2], qa[kk][3], b0, b1);
            }
        }

        if (kt == qt) {
            const int grow_lo = qt * BM + rl;
            const int grow_hi = grow_lo + 8;
#pragma unroll
            for (int nt = 0; nt < 8; nt++) {
                const int col = kt * BN + nt * 8 + 2 * qd;
                if (col     > grow_lo) c[nt][0] = NEG_INF;
                if (col + 1 > grow_lo) c[nt][1] = NEG_INF;
                if (col     > grow_hi) c[nt][2] = NEG_INF;
                if (col + 1 > grow_hi) c[nt][3] = NEG_INF;
            }
        }

        float tlo = NEG_INF, thi = NEG_INF;
#pragma unroll
        for (int nt = 0; nt < 8; nt++) {
            tlo = fmaxf(tlo, fmaxf(c[nt][0], c[nt][1]));
            thi = fmaxf(thi, fmaxf(c[nt][2], c[nt][3]));
        }
        tlo = fmaxf(tlo, __shfl_xor_sync(0xffffffffu, tlo, 1));
        tlo = fmaxf(tlo, __shfl_xor_sync(0xffffffffu, tlo, 2));
        thi = fmaxf(thi, __shfl_xor_sync(0xffffffffu, thi, 1));
        thi = fmaxf(thi, __shfl_xor_sync(0xffffffffu, thi, 2));
        const float mn_lo = fmaxf(m_lo, tlo);
        const float mn_hi = fmaxf(m_hi, thi);
        const float al_lo = __expf(m_lo - mn_lo);
        const float al_hi = __expf(m_hi - mn_hi);
        float s_lo = 0.f, s_hi = 0.f;
#pragma unroll
        for (int nt = 0; nt < 8; nt++) {
            c[nt][0] = __expf(c[nt][0] - mn_lo);
            c[nt][1] = __expf(c[nt][1] - mn_lo);
            c[nt][2] = __expf(c[nt][2] - mn_hi);
            c[nt][3] = __expf(c[nt][3] - mn_hi);
            s_lo += c[nt][0] + c[nt][1];
            s_hi += c[nt][2] + c[nt][3];
        }
        s_lo += __shfl_xor_sync(0xffffffffu, s_lo, 1);
        s_lo += __shfl_xor_sync(0xffffffffu, s_lo, 2);
        s_hi += __shfl_xor_sync(0xffffffffu, s_hi, 1);
        s_hi += __shfl_xor_sync(0xffffffffu, s_hi, 2);
        l_lo = l_lo * al_lo + s_lo;  m_lo = mn_lo;
        l_hi = l_hi * al_hi + s_hi;  m_hi = mn_hi;
#pragma unroll
        for (int t = 0; t < 8; t++) {
            o[t][0] *= al_lo; o[t][1] *= al_lo;
            o[t][2] *= al_hi; o[t][3] *= al_hi;
        }

#pragma unroll
        for (int nt = 0; nt < 8; nt++) {
            *(float2*)&sm[PS_OFF + rl * KST + nt * 8 + 2 * qd]       = make_float2(c[nt][0], c[nt][1]);
            *(float2*)&sm[PS_OFF + (rl + 8) * KST + nt * 8 + 2 * qd] = make_float2(c[nt][2], c[nt][3]);
        }
        __syncwarp();

#pragma unroll
        for (int sc = 0; sc < 8; sc++) {
            const unsigned a0 = f2tf32(sm[PS_OFF + rl * KST + sc * 8 + qd]);
            const unsigned a1 = f2tf32(sm[PS_OFF + (rl + 8) * KST + sc * 8 + qd]);
            const unsigned a2 = f2tf32(sm[PS_OFF + rl * KST + sc * 8 + qd + 4]);
            const unsigned a3 = f2tf32(sm[PS_OFF + (rl + 8) * KST + sc * 8 + qd + 4]);
#pragma unroll
            for (int t = 0; t < 8; t++) {
                const unsigned b0 = __float_as_uint(sm[VS_OFF + (sc * 8 + qd) * VST + t * 8 + grp]);
                const unsigned b1 = __float_as_uint(sm[VS_OFF + (sc * 8 + qd + 4) * VST + t * 8 + grp]);
                mma_tf32(o[t][0], o[t][1], o[t][2], o[t][3], a0, a1, a2, a3, b0, b1);
            }
        }
    }

    const int chunk = rem;
    const int grow_lo = qt * BM + rl;
    float* op = g_op[chunk] + (size_t)b * SEQ * HDIM;
#pragma unroll
    for (int t = 0; t < 8; t++) {
        *(float2*)(op + (size_t)grow_lo * HDIM + t * 8 + 2 * qd) = make_float2(o[t][0], o[t][1]);
        *(float2*)(op + (size_t)(grow_lo + 8) * HDIM + t * 8 + 2 * qd) = make_float2(o[t][2], o[t][3]);
    }
    if (qd == 0) {
        g_pm[chunk][b * SEQ + grow_lo] = m_lo;
        g_pl[chunk][b * SEQ + grow_lo] = l_lo;
        g_pm[chunk][b * SEQ + grow_lo + 8] = m_hi;
        g_pl[chunk][b * SEQ + grow_lo + 8] = l_hi;
    }
}

// ---------------- merge partials ----------------
__global__ __launch_bounds__(256) void merge_partials(float* __restrict__ out) {
    const int g   = blockIdx.x * 256 + threadIdx.x;
    const int row = g >> 2;
    const int d0  = (g & 3) * 16;
    const int t   = row & (SEQ - 1);
    const int qt  = t >> 6;
    const int nc  = (qt + 16) >> 4;

    float mx = __int_as_float(0xff800000);
#pragma unroll
    for (int c = 0; c < NCHUNK_MAX; c++)
        if (c < nc) mx = fmaxf(mx, g_pm[c][row]);

    float w[NCHUNK_MAX];
    float L = 0.f;
#pragma unroll
    for (int c = 0; c < NCHUNK_MAX; c++) {
        w[c] = (c < nc) ? __expf(g_pm[c][row] - mx) : 0.f;
        if (c < nc) L += w[c] * g_pl[c][row];
    }
    const float inv = __fdividef(1.f, L);

#pragma unroll
    for (int v = 0; v < 4; v++) {
        float4 acc = make_float4(0.f, 0.f, 0.f, 0.f);
#pragma unroll
        for (int c = 0; c < NCHUNK_MAX; c++) {
            if (c < nc) {
                const float4 p = *(const float4*)(g_op[c] + (size_t)row * HDIM + d0 + v * 4);
                acc.x = fmaf(w[c], p.x, acc.x);
                acc.y = fmaf(w[c], p.y, acc.y);
                acc.z = fmaf(w[c], p.z, acc.z);
                acc.w = fmaf(w[c], p.w, acc.w);
            }
        }
        acc.x *= inv; acc.y *= inv; acc.z *= inv; acc.w *= inv;
        *(float4*)(out + (size_t)row * HDIM + d0 + v * 4) = acc;
    }
}

extern "C" void kernel_launch(void* const* d_in, const int* in_sizes, int n_in,
                              void* d_out, int out_size) {
    const float* x  = (const float*)d_in[0];
    const float* Wq = (const float*)d_in[1];
    const float* Wk = (const float*)d_in[2];
    const float* Wv = (const float*)d_in[3];
    float* out = (float*)d_out;

    cudaFuncSetAttribute(flash_fwd, cudaFuncAttributeMaxDynamicSharedMemorySize, SMEM_BYTES);
    cudaFuncSetAttribute(qkv_mma, cudaFuncAttributeMaxDynamicSharedMemorySize, QKV_SMEM_BYTES);

    qkv_mma<<<384, 256, QKV_SMEM_BYTES>>>(x, Wq, Wk, Wv);
    flash_fwd<<<BATCH * 160, 128, SMEM_BYTES>>>();
    merge_partials<<<BATCH * SEQ * 4 / 256, 256>>>(out);
}